// round 12
// baseline (speedup 1.0000x reference)
#include <cuda_runtime.h>

#define BB 32
#define NN 128
#define HH 100
#define ROWS (BB*NN)    // 4096

// k_msg w-split tile geometry
#define WH 64           // w-half size
#define EV_STRIDE 258   // u64 per vloc slice of edges (64*4 + 2 pad)
#define MV_STRIDE 66    // u64 per vloc slice of masks (64 + 2 pad)
#define MSG_SMEM_U64 (3200 + 8*EV_STRIDE + 8*MV_STRIDE)   // 5792 u64 = 46336 B

// Scratch (static device allocations — allowed)
__device__ float g_hidden[ROWS*HH];
__device__ float g_hv[ROWS*HH];
__device__ float g_hw[ROWS*HH];
__device__ float g_msg [ROWS*HH];   // w in [0,64)
__device__ float g_msg2[ROWS*HH];   // w in [64,128)
__device__ float g_gterm[ROWS*HH];
__device__ int   g_nodemask[ROWS];

typedef unsigned long long u64;

__device__ __forceinline__ u64 fma2(u64 a, u64 b, u64 c) {
    u64 d;
    asm("fma.rn.f32x2 %0, %1, %2, %3;" : "=l"(d) : "l"(a), "l"(b), "l"(c));
    return d;
}
__device__ __forceinline__ u64 add2(u64 a, u64 b) {
    u64 d;
    asm("add.rn.f32x2 %0, %1, %2;" : "=l"(d) : "l"(a), "l"(b));
    return d;
}
__device__ __forceinline__ u64 pack2(float w) {
    u64 d;
    asm("mov.b64 %0, {%1, %1};" : "=l"(d) : "f"(w));
    return d;
}
__device__ __forceinline__ u64 packlh(float lo, float hi) {
    u64 d;
    asm("mov.b64 %0, {%1, %2};" : "=l"(d) : "f"(lo), "f"(hi));
    return d;
}
__device__ __forceinline__ void unpack2(u64 v, float& lo, float& hi) {
    asm("mov.b64 {%0, %1}, %2;" : "=f"(lo), "=f"(hi) : "l"(v));
}
__device__ __forceinline__ u64 relu2(u64 v) {
    float lo, hi;
    unpack2(v, lo, hi);
    return packlh(fmaxf(lo, 0.f), fmaxf(hi, 0.f));
}

// ---------------------------------------------------------------------------
// init + mask + proj of pass 1. Block = 4 rows, 128 threads, grid 1024.
// ---------------------------------------------------------------------------
__global__ void __launch_bounds__(128)
k_init_proj(const float* __restrict__ nodes, const float* __restrict__ edges,
            const float* __restrict__ Wv, const float* __restrict__ Ww) {
    __shared__ float4 sP[HH];        // nodes transposed: sP[k] = rows 0..3
    int base = blockIdx.x * 4;
    int tid  = threadIdx.x;

    {
        int r = tid >> 5, lane = tid & 31;
        const float4* e4 = (const float4*)edges + (size_t)(base + r) * NN;
        float s = 0.f;
        #pragma unroll
        for (int j = 0; j < 4; j++) {
            float4 e = e4[lane + 32*j];
            s += (e.x + e.y) + (e.z + e.w);
        }
        #pragma unroll
        for (int off = 16; off > 0; off >>= 1)
            s += __shfl_xor_sync(0xffffffffu, s, off);
        if (lane == 0) g_nodemask[base + r] = (s != 0.0f) ? 1 : 0;
    }

    if (tid < HH) {
        int h = tid;
        float x0 = nodes[(size_t)(base+0)*HH + h];
        float x1 = nodes[(size_t)(base+1)*HH + h];
        float x2 = nodes[(size_t)(base+2)*HH + h];
        float x3 = nodes[(size_t)(base+3)*HH + h];
        g_hidden[(size_t)(base+0)*HH + h] = x0;
        g_hidden[(size_t)(base+1)*HH + h] = x1;
        g_hidden[(size_t)(base+2)*HH + h] = x2;
        g_hidden[(size_t)(base+3)*HH + h] = x3;
        sP[h] = make_float4(x0, x1, x2, x3);
    }
    __syncthreads();

    if (tid < HH) {
        int h = tid;
        const ulonglong2* sP2 = (const ulonglong2*)sP;
        u64 v01=0, v23=0, w01=0, w23=0;
        #pragma unroll 4
        for (int k = 0; k < HH; k++) {
            ulonglong2 x = sP2[k];
            u64 wv = pack2(Wv[k*HH + h]);
            u64 ww = pack2(Ww[k*HH + h]);
            v01 = fma2(x.x, wv, v01); v23 = fma2(x.y, wv, v23);
            w01 = fma2(x.x, ww, w01); w23 = fma2(x.y, ww, w23);
        }
        float a,b,c,d, e,f,g,q;
        unpack2(v01, a, b); unpack2(v23, c, d);
        unpack2(w01, e, f); unpack2(w23, g, q);
        g_hv[(size_t)(base+0)*HH + h] = a;
        g_hv[(size_t)(base+1)*HH + h] = b;
        g_hv[(size_t)(base+2)*HH + h] = c;
        g_hv[(size_t)(base+3)*HH + h] = d;
        g_hw[(size_t)(base+0)*HH + h] = e;
        g_hw[(size_t)(base+1)*HH + h] = f;
        g_hw[(size_t)(base+2)*HH + h] = g;
        g_hw[(size_t)(base+3)*HH + h] = q;
    }
}

// ---------------------------------------------------------------------------
// msg (w-split): partial[b,v,h] = sum_{w in half} [adj!=0]*relu(hv+hw+e.We)
// Block = 8 v-rows x one w-half, 256 threads, grid 1024.
// Thread map: warp = one v (vloc = tid>>5), q = tid&31 < 25, h = 4q..4q+3
// (2 h-pairs per thread). Edge/mask LDS are same-address broadcasts within
// a warp (1 wf, conflict-free by construction); hw read as one LDS.128.
// smem 46336 B -> 4 blocks/SM.
// ---------------------------------------------------------------------------
__global__ void __launch_bounds__(256)
k_msg(const float* __restrict__ edges, const float* __restrict__ We) {
    extern __shared__ u64 sm[];
    u64* s_hw2 = sm;                        // [wl*50 + p]
    u64* s_e2  = sm + 3200;                 // [v*EV_STRIDE + wl*4 + j]
    u64* s_m2  = sm + 3200 + 8*EV_STRIDE;   // [v*MV_STRIDE + wl]

    int bx   = blockIdx.x;
    int half = bx & 1;
    int v0   = ((bx >> 1) & 15) * 8;
    int b    = bx >> 5;
    int wofs = half * WH;
    int tid  = threadIdx.x;
    int bN   = b * NN;
    float* outp = half ? g_msg2 : g_msg;

    // stage hw pairs for this w-half (64 rows x 50 pairs)
    for (int i = tid; i < WH*50; i += 256) {
        int wl = i / 50, p = i - wl*50;
        s_hw2[i] = *(const u64*)(g_hw + (size_t)(bN + wofs + wl)*HH + 2*p);
    }
    // stage edges (dup'd) + masks (dup'd) for 8 v-rows x 64 w
    for (int i = tid; i < 8*WH; i += 256) {
        int v = i >> 6, wl = i & 63;
        float4 e = ((const float4*)edges)[(size_t)(bN + v0 + v)*NN + wofs + wl];
        u64* dst = s_e2 + v*EV_STRIDE + wl*4;
        dst[0] = pack2(e.x); dst[1] = pack2(e.y);
        dst[2] = pack2(e.z); dst[3] = pack2(e.w);
        float s = (e.x + e.y) + (e.z + e.w);
        s_m2[v*MV_STRIDE + wl] = pack2((s != 0.0f) ? 1.0f : 0.0f);
    }
    __syncthreads();

    int vloc = tid >> 5;
    int q    = tid & 31;
    if (q < 25) {
        int h0  = 4*q;
        int row = bN + v0 + vloc;
        // hv pairs for h0..h3
        float4 hv4 = *(const float4*)(g_hv + (size_t)row*HH + h0);
        u64 hv01 = packlh(hv4.x, hv4.y);
        u64 hv23 = packlh(hv4.z, hv4.w);
        // We pairs for both h-pairs
        float4 w0 = *(const float4*)(We + 0*HH + h0);
        float4 w1 = *(const float4*)(We + 1*HH + h0);
        float4 w2 = *(const float4*)(We + 2*HH + h0);
        float4 w3 = *(const float4*)(We + 3*HH + h0);
        u64 we0a = packlh(w0.x, w0.y), we0b = packlh(w0.z, w0.w);
        u64 we1a = packlh(w1.x, w1.y), we1b = packlh(w1.z, w1.w);
        u64 we2a = packlh(w2.x, w2.y), we2b = packlh(w2.z, w2.w);
        u64 we3a = packlh(w3.x, w3.y), we3b = packlh(w3.z, w3.w);

        const u64* ev  = s_e2 + vloc*EV_STRIDE;
        const u64* mv  = s_m2 + vloc*MV_STRIDE;
        const u64* hwp = s_hw2 + 2*q;

        u64 acc01a = 0, acc23a = 0, acc01b = 0, acc23b = 0;
        #pragma unroll 2
        for (int wl = 0; wl < WH; wl += 2) {
            // wl
            {
                ulonglong2 hw = *(const ulonglong2*)(hwp + wl*50);
                ulonglong2 eA = *(const ulonglong2*)(ev + wl*4);
                ulonglong2 eB = *(const ulonglong2*)(ev + wl*4 + 2);
                u64 m2v = mv[wl];
                u64 p01 = add2(hv01, hw.x);
                u64 p23 = add2(hv23, hw.y);
                p01 = fma2(eA.x, we0a, p01); p23 = fma2(eA.x, we0b, p23);
                p01 = fma2(eA.y, we1a, p01); p23 = fma2(eA.y, we1b, p23);
                p01 = fma2(eB.x, we2a, p01); p23 = fma2(eB.x, we2b, p23);
                p01 = fma2(eB.y, we3a, p01); p23 = fma2(eB.y, we3b, p23);
                acc01a = fma2(relu2(p01), m2v, acc01a);
                acc23a = fma2(relu2(p23), m2v, acc23a);
            }
            // wl+1 (independent chains)
            {
                ulonglong2 hw = *(const ulonglong2*)(hwp + (wl+1)*50);
                ulonglong2 eA = *(const ulonglong2*)(ev + (wl+1)*4);
                ulonglong2 eB = *(const ulonglong2*)(ev + (wl+1)*4 + 2);
                u64 m2v = mv[wl+1];
                u64 p01 = add2(hv01, hw.x);
                u64 p23 = add2(hv23, hw.y);
                p01 = fma2(eA.x, we0a, p01); p23 = fma2(eA.x, we0b, p23);
                p01 = fma2(eA.y, we1a, p01); p23 = fma2(eA.y, we1b, p23);
                p01 = fma2(eB.x, we2a, p01); p23 = fma2(eB.x, we2b, p23);
                p01 = fma2(eB.y, we3a, p01); p23 = fma2(eB.y, we3b, p23);
                acc01b = fma2(relu2(p01), m2v, acc01b);
                acc23b = fma2(relu2(p23), m2v, acc23b);
            }
        }
        u64 acc01 = add2(acc01a, acc01b);
        u64 acc23 = add2(acc23a, acc23b);
        float4 outv;
        unpack2(acc01, outv.x, outv.y);
        unpack2(acc23, outv.z, outv.w);
        *(float4*)(outp + (size_t)row*HH + h0) = outv;
    }
}

// ---------------------------------------------------------------------------
// update (masked tanh) fused with proj of the NEW hidden. 4 rows, 128 thr,
// grid 1024. msg = g_msg + g_msg2 (the two w-half partials).
// ---------------------------------------------------------------------------
__global__ void __launch_bounds__(128)
k_updproj(const float* __restrict__ Wu, const float* __restrict__ Wv,
          const float* __restrict__ Ww) {
    __shared__ float4 sU[2*HH];      // [hidden; msg] transposed
    __shared__ float4 sP[HH];        // new hidden transposed
    int base = blockIdx.x * 4;
    int tid  = threadIdx.x;
    float* sUf = (float*)sU;

    for (int i = tid; i < 4*2*HH; i += 128) {
        int r = i / (2*HH), k = i - r*(2*HH);
        size_t idx = (size_t)(base + r)*HH;
        float x = (k < HH) ? g_hidden[idx + k]
                           : (g_msg[idx + (k - HH)] + g_msg2[idx + (k - HH)]);
        sUf[k*4 + r] = x;
    }
    __syncthreads();

    if (tid < HH) {
        int h = tid;
        const ulonglong2* sU2 = (const ulonglong2*)sU;
        u64 a01=0, a23=0;
        #pragma unroll 4
        for (int k = 0; k < 2*HH; k++) {
            ulonglong2 x = sU2[k];
            u64 w = pack2(Wu[k*HH + h]);
            a01 = fma2(x.x, w, a01);
            a23 = fma2(x.y, w, a23);
        }
        float f0,f1,f2,f3;
        unpack2(a01, f0, f1); unpack2(a23, f2, f3);
        float n0 = g_nodemask[base+0] ? tanhf(f0) : sUf[h*4+0];
        float n1 = g_nodemask[base+1] ? tanhf(f1) : sUf[h*4+1];
        float n2 = g_nodemask[base+2] ? tanhf(f2) : sUf[h*4+2];
        float n3 = g_nodemask[base+3] ? tanhf(f3) : sUf[h*4+3];
        g_hidden[(size_t)(base+0)*HH + h] = n0;
        g_hidden[(size_t)(base+1)*HH + h] = n1;
        g_hidden[(size_t)(base+2)*HH + h] = n2;
        g_hidden[(size_t)(base+3)*HH + h] = n3;
        sP[h] = make_float4(n0, n1, n2, n3);
    }
    __syncthreads();

    if (tid < HH) {
        int h = tid;
        const ulonglong2* sP2 = (const ulonglong2*)sP;
        u64 v01=0, v23=0, w01=0, w23=0;
        #pragma unroll 4
        for (int k = 0; k < HH; k++) {
            ulonglong2 x = sP2[k];
            u64 wv = pack2(Wv[k*HH + h]);
            u64 ww = pack2(Ww[k*HH + h]);
            v01 = fma2(x.x, wv, v01); v23 = fma2(x.y, wv, v23);
            w01 = fma2(x.x, ww, w01); w23 = fma2(x.y, ww, w23);
        }
        float a,b,c,d, e,f,g,q;
        unpack2(v01, a, b); unpack2(v23, c, d);
        unpack2(w01, e, f); unpack2(w23, g, q);
        g_hv[(size_t)(base+0)*HH + h] = a;
        g_hv[(size_t)(base+1)*HH + h] = b;
        g_hv[(size_t)(base+2)*HH + h] = c;
        g_hv[(size_t)(base+3)*HH + h] = d;
        g_hw[(size_t)(base+0)*HH + h] = e;
        g_hw[(size_t)(base+1)*HH + h] = f;
        g_hw[(size_t)(base+2)*HH + h] = g;
        g_hw[(size_t)(base+3)*HH + h] = q;
    }
}

// ---------------------------------------------------------------------------
// final update fused with readout gterm. No g_hidden write needed.
// ---------------------------------------------------------------------------
__global__ void __launch_bounds__(128)
k_updread(const float* __restrict__ nodes, const float* __restrict__ Wu,
          const float* __restrict__ Wr) {
    __shared__ float4 sU[2*HH];      // [hidden; msg]
    __shared__ float4 sR[2*HH];      // [new_hidden; nodes]
    int base = blockIdx.x * 4;
    int tid  = threadIdx.x;
    float* sUf = (float*)sU;
    float* sRf = (float*)sR;

    for (int i = tid; i < 4*2*HH; i += 128) {
        int r = i / (2*HH), k = i - r*(2*HH);
        size_t idx = (size_t)(base + r)*HH;
        float x = (k < HH) ? g_hidden[idx + k]
                           : (g_msg[idx + (k - HH)] + g_msg2[idx + (k - HH)]);
        sUf[k*4 + r] = x;
    }
    for (int i = tid; i < 4*HH; i += 128) {
        int r = i / HH, k = i - r*HH;
        sRf[(HH + k)*4 + r] = nodes[(size_t)(base + r)*HH + k];
    }
    __syncthreads();

    if (tid < HH) {
        int h = tid;
        const ulonglong2* sU2 = (const ulonglong2*)sU;
        u64 a01=0, a23=0;
        #pragma unroll 4
        for (int k = 0; k < 2*HH; k++) {
            ulonglong2 x = sU2[k];
            u64 w = pack2(Wu[k*HH + h]);
            a01 = fma2(x.x, w, a01);
            a23 = fma2(x.y, w, a23);
        }
        float f0,f1,f2,f3;
        unpack2(a01, f0, f1); unpack2(a23, f2, f3);
        float n0 = g_nodemask[base+0] ? tanhf(f0) : sUf[h*4+0];
        float n1 = g_nodemask[base+1] ? tanhf(f1) : sUf[h*4+1];
        float n2 = g_nodemask[base+2] ? tanhf(f2) : sUf[h*4+2];
        float n3 = g_nodemask[base+3] ? tanhf(f3) : sUf[h*4+3];
        sR[h] = make_float4(n0, n1, n2, n3);
    }
    __syncthreads();

    if (tid < HH) {
        int h = tid;
        const ulonglong2* sR2 = (const ulonglong2*)sR;
        u64 a01=0, a23=0;
        #pragma unroll 4
        for (int k = 0; k < 2*HH; k++) {
            ulonglong2 x = sR2[k];
            u64 w = pack2(Wr[k*HH + h]);
            a01 = fma2(x.x, w, a01);
            a23 = fma2(x.y, w, a23);
        }
        float f0,f1,f2,f3;
        unpack2(a01, f0, f1); unpack2(a23, f2, f3);
        float m0 = g_nodemask[base+0] ? 1.f : 0.f;
        float m1 = g_nodemask[base+1] ? 1.f : 0.f;
        float m2 = g_nodemask[base+2] ? 1.f : 0.f;
        float m3 = g_nodemask[base+3] ? 1.f : 0.f;
        g_gterm[(size_t)(base+0)*HH + h] = fmaxf(f0, 0.f) * m0;
        g_gterm[(size_t)(base+1)*HH + h] = fmaxf(f1, 0.f) * m1;
        g_gterm[(size_t)(base+2)*HH + h] = fmaxf(f2, 0.f) * m2;
        g_gterm[(size_t)(base+3)*HH + h] = fmaxf(f3, 0.f) * m3;
    }
}

// ---------------------------------------------------------------------------
// reduce: out[b,h] = sum_v gterm[b,v,h]  (deterministic, no atomics)
// ---------------------------------------------------------------------------
__global__ void k_reduce(float* __restrict__ out) {
    int b   = blockIdx.x;
    int tid = threadIdx.x;           // 512
    int q   = tid >> 7;
    int h   = tid & 127;
    __shared__ float red[4][128];
    float acc = 0.f;
    if (h < HH) {
        int v0 = q * 32;
        #pragma unroll 4
        for (int v = v0; v < v0 + 32; v++)
            acc += g_gterm[(size_t)(b*NN + v)*HH + h];
    }
    red[q][h] = acc;
    __syncthreads();
    if (q == 0 && h < HH)
        out[b*HH + h] = (red[0][h] + red[1][h]) + (red[2][h] + red[3][h]);
}

extern "C" void kernel_launch(void* const* d_in, const int* in_sizes, int n_in,
                              void* d_out, int out_size) {
    const float* nodes = (const float*)d_in[0];
    const float* edges = (const float*)d_in[1];
    const float* Wv    = (const float*)d_in[2];
    const float* Ww    = (const float*)d_in[3];
    const float* We    = (const float*)d_in[4];
    const float* Wu    = (const float*)d_in[5];
    const float* Wr    = (const float*)d_in[6];
    float* out = (float*)d_out;

    const int msg_smem = MSG_SMEM_U64 * 8;   // 46336 B
    cudaFuncSetAttribute(k_msg, cudaFuncAttributeMaxDynamicSharedMemorySize, msg_smem);

    k_init_proj<<<ROWS/4, 128>>>(nodes, edges, Wv, Ww);
    for (int p = 0; p < 2; p++) {
        k_msg<<<1024, 256, msg_smem>>>(edges, We);
        k_updproj<<<ROWS/4, 128>>>(Wu, Wv, Ww);
    }
    k_msg<<<1024, 256, msg_smem>>>(edges, We);
    k_updread<<<ROWS/4, 128>>>(nodes, Wu, Wr);
    k_reduce<<<BB, 512>>>(out);
}

// round 13
// speedup vs baseline: 1.0373x; 1.0373x over previous
#include <cuda_runtime.h>

#define BB 32
#define NN 128
#define HH 100
#define ROWS (BB*NN)    // 4096

// k_msg w-split tile geometry
#define WH 64           // w-half size
// smem (u64 units): hw pairs 3200 | e float4 1024 | m2 512  = 4736 u64 = 37888 B
#define MSG_SMEM_U64 (3200 + 1024 + 512)

// Scratch (static device allocations — allowed)
__device__ float g_hidden[ROWS*HH];
__device__ float g_hv[ROWS*HH];
__device__ float g_hw[ROWS*HH];
__device__ float g_msg [ROWS*HH];   // w in [0,64)
__device__ float g_msg2[ROWS*HH];   // w in [64,128)
__device__ float g_gterm[ROWS*HH];
__device__ int   g_nodemask[ROWS];
__device__ unsigned long long g_mask2[ROWS*NN];   // {m,m} per (b,v,w), 4MB

typedef unsigned long long u64;

__device__ __forceinline__ u64 fma2(u64 a, u64 b, u64 c) {
    u64 d;
    asm("fma.rn.f32x2 %0, %1, %2, %3;" : "=l"(d) : "l"(a), "l"(b), "l"(c));
    return d;
}
__device__ __forceinline__ u64 add2(u64 a, u64 b) {
    u64 d;
    asm("add.rn.f32x2 %0, %1, %2;" : "=l"(d) : "l"(a), "l"(b));
    return d;
}
__device__ __forceinline__ u64 pack2(float w) {
    u64 d;
    asm("mov.b64 %0, {%1, %1};" : "=l"(d) : "f"(w));
    return d;
}
__device__ __forceinline__ u64 packlh(float lo, float hi) {
    u64 d;
    asm("mov.b64 %0, {%1, %2};" : "=l"(d) : "f"(lo), "f"(hi));
    return d;
}
__device__ __forceinline__ void unpack2(u64 v, float& lo, float& hi) {
    asm("mov.b64 {%0, %1}, %2;" : "=f"(lo), "=f"(hi) : "l"(v));
}
__device__ __forceinline__ u64 relu2(u64 v) {
    float lo, hi;
    unpack2(v, lo, hi);
    return packlh(fmaxf(lo, 0.f), fmaxf(hi, 0.f));
}

// ---------------------------------------------------------------------------
// init + node/edge masks + proj of pass 1. Block = 4 rows, 128 thr, grid 1024.
// Also writes g_mask2[(row,w)] = {m,m} (edge mask), consumed by all k_msg.
// ---------------------------------------------------------------------------
__global__ void __launch_bounds__(128)
k_init_proj(const float* __restrict__ nodes, const float* __restrict__ edges,
            const float* __restrict__ Wv, const float* __restrict__ Ww) {
    __shared__ float4 sP[HH];        // nodes transposed: sP[k] = rows 0..3
    int base = blockIdx.x * 4;
    int tid  = threadIdx.x;

    {
        int r = tid >> 5, lane = tid & 31;
        const float4* e4 = (const float4*)edges + (size_t)(base + r) * NN;
        float s = 0.f;
        #pragma unroll
        for (int j = 0; j < 4; j++) {
            float4 e = e4[lane + 32*j];
            float sj = (e.x + e.y) + (e.z + e.w);
            g_mask2[(size_t)(base + r)*NN + lane + 32*j] =
                pack2((sj != 0.0f) ? 1.0f : 0.0f);
            s += sj;
        }
        #pragma unroll
        for (int off = 16; off > 0; off >>= 1)
            s += __shfl_xor_sync(0xffffffffu, s, off);
        if (lane == 0) g_nodemask[base + r] = (s != 0.0f) ? 1 : 0;
    }

    if (tid < HH) {
        int h = tid;
        float x0 = nodes[(size_t)(base+0)*HH + h];
        float x1 = nodes[(size_t)(base+1)*HH + h];
        float x2 = nodes[(size_t)(base+2)*HH + h];
        float x3 = nodes[(size_t)(base+3)*HH + h];
        g_hidden[(size_t)(base+0)*HH + h] = x0;
        g_hidden[(size_t)(base+1)*HH + h] = x1;
        g_hidden[(size_t)(base+2)*HH + h] = x2;
        g_hidden[(size_t)(base+3)*HH + h] = x3;
        sP[h] = make_float4(x0, x1, x2, x3);
    }
    __syncthreads();

    if (tid < HH) {
        int h = tid;
        const ulonglong2* sP2 = (const ulonglong2*)sP;
        u64 v01=0, v23=0, w01=0, w23=0;
        #pragma unroll 4
        for (int k = 0; k < HH; k++) {
            ulonglong2 x = sP2[k];
            u64 wv = pack2(Wv[k*HH + h]);
            u64 ww = pack2(Ww[k*HH + h]);
            v01 = fma2(x.x, wv, v01); v23 = fma2(x.y, wv, v23);
            w01 = fma2(x.x, ww, w01); w23 = fma2(x.y, ww, w23);
        }
        float a,b,c,d, e,f,g,q;
        unpack2(v01, a, b); unpack2(v23, c, d);
        unpack2(w01, e, f); unpack2(w23, g, q);
        g_hv[(size_t)(base+0)*HH + h] = a;
        g_hv[(size_t)(base+1)*HH + h] = b;
        g_hv[(size_t)(base+2)*HH + h] = c;
        g_hv[(size_t)(base+3)*HH + h] = d;
        g_hw[(size_t)(base+0)*HH + h] = e;
        g_hw[(size_t)(base+1)*HH + h] = f;
        g_hw[(size_t)(base+2)*HH + h] = g;
        g_hw[(size_t)(base+3)*HH + h] = q;
    }
}

// ---------------------------------------------------------------------------
// msg (w-split): partial[b,v,h] = sum_{w in half} [adj!=0]*relu(hv+hw+e.We)
// Block = 8 v-rows x one w-half, 256 threads, grid 1024.
// Thread map: warp = one v (vloc = tid>>5), q = tid&31 < 25, h = 4q..4q+3.
// Edges stored UNduplicated (float4, 1 LDS.128 broadcast + 4 alu MOV packs);
// mask pre-dup'd u64 (copied from g_mask2). LDS per w: 3 (was 4).
// smem 37888 B; __launch_bounds__(256,4) pins 4 blocks/SM.
// ---------------------------------------------------------------------------
__global__ void __launch_bounds__(256, 4)
k_msg(const float* __restrict__ edges, const float* __restrict__ We) {
    extern __shared__ u64 sm[];
    u64*    s_hw2 = sm;                    // [wl*50 + p]
    float4* s_e4  = (float4*)(sm + 3200);  // [v*64 + wl]
    u64*    s_m2  = sm + 3200 + 1024;      // [v*64 + wl]

    int bx   = blockIdx.x;
    int half = bx & 1;
    int v0   = ((bx >> 1) & 15) * 8;
    int b    = bx >> 5;
    int wofs = half * WH;
    int tid  = threadIdx.x;
    int bN   = b * NN;
    float* outp = half ? g_msg2 : g_msg;

    // stage hw pairs for this w-half (64 rows x 50 pairs)
    for (int i = tid; i < WH*50; i += 256) {
        int wl = i / 50, p = i - wl*50;
        s_hw2[i] = *(const u64*)(g_hw + (size_t)(bN + wofs + wl)*HH + 2*p);
    }
    // stage edges (plain float4) + masks (pre-dup'd) for 8 v-rows x 64 w
    for (int i = tid; i < 8*WH; i += 256) {
        int v = i >> 6, wl = i & 63;
        size_t gofs = (size_t)(bN + v0 + v)*NN + wofs + wl;
        s_e4[i] = ((const float4*)edges)[gofs];
        s_m2[i] = g_mask2[gofs];
    }
    __syncthreads();

    int vloc = tid >> 5;
    int q    = tid & 31;
    if (q < 25) {
        int h0  = 4*q;
        int row = bN + v0 + vloc;
        float4 hv4 = *(const float4*)(g_hv + (size_t)row*HH + h0);
        u64 hv01 = packlh(hv4.x, hv4.y);
        u64 hv23 = packlh(hv4.z, hv4.w);
        float4 w0 = *(const float4*)(We + 0*HH + h0);
        float4 w1 = *(const float4*)(We + 1*HH + h0);
        float4 w2 = *(const float4*)(We + 2*HH + h0);
        float4 w3 = *(const float4*)(We + 3*HH + h0);
        u64 we0a = packlh(w0.x, w0.y), we0b = packlh(w0.z, w0.w);
        u64 we1a = packlh(w1.x, w1.y), we1b = packlh(w1.z, w1.w);
        u64 we2a = packlh(w2.x, w2.y), we2b = packlh(w2.z, w2.w);
        u64 we3a = packlh(w3.x, w3.y), we3b = packlh(w3.z, w3.w);

        const float4* ev = s_e4  + vloc*WH;
        const u64*    mv = s_m2  + vloc*WH;
        const u64*   hwp = s_hw2 + 2*q;

        u64 acc01a = 0, acc23a = 0, acc01b = 0, acc23b = 0;
        #pragma unroll 2
        for (int wl = 0; wl < WH; wl += 2) {
            {
                float4 e = ev[wl];
                u64 e0 = pack2(e.x), e1 = pack2(e.y);
                u64 e2 = pack2(e.z), e3 = pack2(e.w);
                ulonglong2 hw = *(const ulonglong2*)(hwp + wl*50);
                u64 m2v = mv[wl];
                u64 p01 = add2(hv01, hw.x);
                u64 p23 = add2(hv23, hw.y);
                p01 = fma2(e0, we0a, p01); p23 = fma2(e0, we0b, p23);
                p01 = fma2(e1, we1a, p01); p23 = fma2(e1, we1b, p23);
                p01 = fma2(e2, we2a, p01); p23 = fma2(e2, we2b, p23);
                p01 = fma2(e3, we3a, p01); p23 = fma2(e3, we3b, p23);
                acc01a = fma2(relu2(p01), m2v, acc01a);
                acc23a = fma2(relu2(p23), m2v, acc23a);
            }
            {
                float4 e = ev[wl+1];
                u64 e0 = pack2(e.x), e1 = pack2(e.y);
                u64 e2 = pack2(e.z), e3 = pack2(e.w);
                ulonglong2 hw = *(const ulonglong2*)(hwp + (wl+1)*50);
                u64 m2v = mv[wl+1];
                u64 p01 = add2(hv01, hw.x);
                u64 p23 = add2(hv23, hw.y);
                p01 = fma2(e0, we0a, p01); p23 = fma2(e0, we0b, p23);
                p01 = fma2(e1, we1a, p01); p23 = fma2(e1, we1b, p23);
                p01 = fma2(e2, we2a, p01); p23 = fma2(e2, we2b, p23);
                p01 = fma2(e3, we3a, p01); p23 = fma2(e3, we3b, p23);
                acc01b = fma2(relu2(p01), m2v, acc01b);
                acc23b = fma2(relu2(p23), m2v, acc23b);
            }
        }
        u64 acc01 = add2(acc01a, acc01b);
        u64 acc23 = add2(acc23a, acc23b);
        float4 outv;
        unpack2(acc01, outv.x, outv.y);
        unpack2(acc23, outv.z, outv.w);
        *(float4*)(outp + (size_t)row*HH + h0) = outv;
    }
}

// ---------------------------------------------------------------------------
// update (masked tanh) fused with proj of the NEW hidden. 4 rows, 128 thr,
// grid 1024. msg = g_msg + g_msg2 (the two w-half partials).
// ---------------------------------------------------------------------------
__global__ void __launch_bounds__(128)
k_updproj(const float* __restrict__ Wu, const float* __restrict__ Wv,
          const float* __restrict__ Ww) {
    __shared__ float4 sU[2*HH];      // [hidden; msg] transposed
    __shared__ float4 sP[HH];        // new hidden transposed
    int base = blockIdx.x * 4;
    int tid  = threadIdx.x;
    float* sUf = (float*)sU;

    for (int i = tid; i < 4*2*HH; i += 128) {
        int r = i / (2*HH), k = i - r*(2*HH);
        size_t idx = (size_t)(base + r)*HH;
        float x = (k < HH) ? g_hidden[idx + k]
                           : (g_msg[idx + (k - HH)] + g_msg2[idx + (k - HH)]);
        sUf[k*4 + r] = x;
    }
    __syncthreads();

    if (tid < HH) {
        int h = tid;
        const ulonglong2* sU2 = (const ulonglong2*)sU;
        u64 a01=0, a23=0;
        #pragma unroll 4
        for (int k = 0; k < 2*HH; k++) {
            ulonglong2 x = sU2[k];
            u64 w = pack2(Wu[k*HH + h]);
            a01 = fma2(x.x, w, a01);
            a23 = fma2(x.y, w, a23);
        }
        float f0,f1,f2,f3;
        unpack2(a01, f0, f1); unpack2(a23, f2, f3);
        float n0 = g_nodemask[base+0] ? tanhf(f0) : sUf[h*4+0];
        float n1 = g_nodemask[base+1] ? tanhf(f1) : sUf[h*4+1];
        float n2 = g_nodemask[base+2] ? tanhf(f2) : sUf[h*4+2];
        float n3 = g_nodemask[base+3] ? tanhf(f3) : sUf[h*4+3];
        g_hidden[(size_t)(base+0)*HH + h] = n0;
        g_hidden[(size_t)(base+1)*HH + h] = n1;
        g_hidden[(size_t)(base+2)*HH + h] = n2;
        g_hidden[(size_t)(base+3)*HH + h] = n3;
        sP[h] = make_float4(n0, n1, n2, n3);
    }
    __syncthreads();

    if (tid < HH) {
        int h = tid;
        const ulonglong2* sP2 = (const ulonglong2*)sP;
        u64 v01=0, v23=0, w01=0, w23=0;
        #pragma unroll 4
        for (int k = 0; k < HH; k++) {
            ulonglong2 x = sP2[k];
            u64 wv = pack2(Wv[k*HH + h]);
            u64 ww = pack2(Ww[k*HH + h]);
            v01 = fma2(x.x, wv, v01); v23 = fma2(x.y, wv, v23);
            w01 = fma2(x.x, ww, w01); w23 = fma2(x.y, ww, w23);
        }
        float a,b,c,d, e,f,g,q;
        unpack2(v01, a, b); unpack2(v23, c, d);
        unpack2(w01, e, f); unpack2(w23, g, q);
        g_hv[(size_t)(base+0)*HH + h] = a;
        g_hv[(size_t)(base+1)*HH + h] = b;
        g_hv[(size_t)(base+2)*HH + h] = c;
        g_hv[(size_t)(base+3)*HH + h] = d;
        g_hw[(size_t)(base+0)*HH + h] = e;
        g_hw[(size_t)(base+1)*HH + h] = f;
        g_hw[(size_t)(base+2)*HH + h] = g;
        g_hw[(size_t)(base+3)*HH + h] = q;
    }
}

// ---------------------------------------------------------------------------
// final update fused with readout gterm. No g_hidden write needed.
// ---------------------------------------------------------------------------
__global__ void __launch_bounds__(128)
k_updread(const float* __restrict__ nodes, const float* __restrict__ Wu,
          const float* __restrict__ Wr) {
    __shared__ float4 sU[2*HH];      // [hidden; msg]
    __shared__ float4 sR[2*HH];      // [new_hidden; nodes]
    int base = blockIdx.x * 4;
    int tid  = threadIdx.x;
    float* sUf = (float*)sU;
    float* sRf = (float*)sR;

    for (int i = tid; i < 4*2*HH; i += 128) {
        int r = i / (2*HH), k = i - r*(2*HH);
        size_t idx = (size_t)(base + r)*HH;
        float x = (k < HH) ? g_hidden[idx + k]
                           : (g_msg[idx + (k - HH)] + g_msg2[idx + (k - HH)]);
        sUf[k*4 + r] = x;
    }
    for (int i = tid; i < 4*HH; i += 128) {
        int r = i / HH, k = i - r*HH;
        sRf[(HH + k)*4 + r] = nodes[(size_t)(base + r)*HH + k];
    }
    __syncthreads();

    if (tid < HH) {
        int h = tid;
        const ulonglong2* sU2 = (const ulonglong2*)sU;
        u64 a01=0, a23=0;
        #pragma unroll 4
        for (int k = 0; k < 2*HH; k++) {
            ulonglong2 x = sU2[k];
            u64 w = pack2(Wu[k*HH + h]);
            a01 = fma2(x.x, w, a01);
            a23 = fma2(x.y, w, a23);
        }
        float f0,f1,f2,f3;
        unpack2(a01, f0, f1); unpack2(a23, f2, f3);
        float n0 = g_nodemask[base+0] ? tanhf(f0) : sUf[h*4+0];
        float n1 = g_nodemask[base+1] ? tanhf(f1) : sUf[h*4+1];
        float n2 = g_nodemask[base+2] ? tanhf(f2) : sUf[h*4+2];
        float n3 = g_nodemask[base+3] ? tanhf(f3) : sUf[h*4+3];
        sR[h] = make_float4(n0, n1, n2, n3);
    }
    __syncthreads();

    if (tid < HH) {
        int h = tid;
        const ulonglong2* sR2 = (const ulonglong2*)sR;
        u64 a01=0, a23=0;
        #pragma unroll 4
        for (int k = 0; k < 2*HH; k++) {
            ulonglong2 x = sR2[k];
            u64 w = pack2(Wr[k*HH + h]);
            a01 = fma2(x.x, w, a01);
            a23 = fma2(x.y, w, a23);
        }
        float f0,f1,f2,f3;
        unpack2(a01, f0, f1); unpack2(a23, f2, f3);
        float m0 = g_nodemask[base+0] ? 1.f : 0.f;
        float m1 = g_nodemask[base+1] ? 1.f : 0.f;
        float m2 = g_nodemask[base+2] ? 1.f : 0.f;
        float m3 = g_nodemask[base+3] ? 1.f : 0.f;
        g_gterm[(size_t)(base+0)*HH + h] = fmaxf(f0, 0.f) * m0;
        g_gterm[(size_t)(base+1)*HH + h] = fmaxf(f1, 0.f) * m1;
        g_gterm[(size_t)(base+2)*HH + h] = fmaxf(f2, 0.f) * m2;
        g_gterm[(size_t)(base+3)*HH + h] = fmaxf(f3, 0.f) * m3;
    }
}

// ---------------------------------------------------------------------------
// reduce: out[b,h] = sum_v gterm[b,v,h]  (deterministic, no atomics)
// ---------------------------------------------------------------------------
__global__ void k_reduce(float* __restrict__ out) {
    int b   = blockIdx.x;
    int tid = threadIdx.x;           // 512
    int q   = tid >> 7;
    int h   = tid & 127;
    __shared__ float red[4][128];
    float acc = 0.f;
    if (h < HH) {
        int v0 = q * 32;
        #pragma unroll 4
        for (int v = v0; v < v0 + 32; v++)
            acc += g_gterm[(size_t)(b*NN + v)*HH + h];
    }
    red[q][h] = acc;
    __syncthreads();
    if (q == 0 && h < HH)
        out[b*HH + h] = (red[0][h] + red[1][h]) + (red[2][h] + red[3][h]);
}

extern "C" void kernel_launch(void* const* d_in, const int* in_sizes, int n_in,
                              void* d_out, int out_size) {
    const float* nodes = (const float*)d_in[0];
    const float* edges = (const float*)d_in[1];
    const float* Wv    = (const float*)d_in[2];
    const float* Ww    = (const float*)d_in[3];
    const float* We    = (const float*)d_in[4];
    const float* Wu    = (const float*)d_in[5];
    const float* Wr    = (const float*)d_in[6];
    float* out = (float*)d_out;

    const int msg_smem = MSG_SMEM_U64 * 8;   // 37888 B
    cudaFuncSetAttribute(k_msg, cudaFuncAttributeMaxDynamicSharedMemorySize, msg_smem);

    k_init_proj<<<ROWS/4, 128>>>(nodes, edges, Wv, Ww);
    for (int p = 0; p < 2; p++) {
        k_msg<<<1024, 256, msg_smem>>>(edges, We);
        k_updproj<<<ROWS/4, 128>>>(Wu, Wv, Ww);
    }
    k_msg<<<1024, 256, msg_smem>>>(edges, We);
    k_updread<<<ROWS/4, 128>>>(nodes, Wu, Wr);
    k_reduce<<<BB, 512>>>(out);
}